// round 5
// baseline (speedup 1.0000x reference)
#include <cuda_runtime.h>
#include <math.h>

typedef unsigned long long u64;

__device__ __forceinline__ u64 pack2(float v) {
    u64 r; asm("mov.b64 %0, {%1, %1};" : "=l"(r) : "f"(v)); return r;
}
__device__ __forceinline__ u64 ffma2(u64 a, u64 b, u64 c) {
    u64 d; asm("fma.rn.f32x2 %0, %1, %2, %3;" : "=l"(d) : "l"(a), "l"(b), "l"(c)); return d;
}
__device__ __forceinline__ float2 unpack2(u64 a) {
    float2 f; asm("mov.b64 {%0, %1}, %2;" : "=f"(f.x), "=f"(f.y) : "l"(a)); return f;
}

// ---------------------------------------------------------------------------
// Scratch arena. Activations are halo-padded: dim D stored as P=D+2 with a
// one-voxel zero halo; interior voxel (z,y,x) at ((z+1)*P+(y+1))*P+(x+1).
// ---------------------------------------------------------------------------
constexpr int OX0  = 0;          // 2*4*66^3   = 2299968
constexpr int OZ1  = 2299968;    // 2*32*34^3  = 2515456
constexpr int OZ2  = 4815424;    // 2*64*18^3  = 746496
constexpr int OZ3  = 5561920;    // 2*128*10^3 = 256000
constexpr int OZ4  = 5817920;    // 2*128*18^3 = 1492992
constexpr int OZ5  = 7310912;    // 2*64*32^3  = 4194304 (unpadded)
constexpr int OM0  = 11505216;   // 2*64^3
constexpr int OM1  = 12029504;   // 2*32^3
constexpr int OM2  = 12095040;   // 2*16^3
constexpr int OM3  = 12103232;   // 2*8^3
constexpr int OM4  = 12104256;   // 2*16^3
constexpr int OM5  = 12112448;   // 2*32^3
constexpr int OW1  = 12177984;   // 8192
constexpr int OW2  = 12186176;   // 131072
constexpr int OW3  = 12317248;   // 524288
constexpr int OTW1 = 12841536;   // 1048576
constexpr int OTW2 = 13890112;   // 524288
constexpr int OFW  = 14414400;   // 2048
constexpr int OST  = 14416448;   // 5*260
constexpr int TOT_SCRATCH = 14417920;

__device__ float g_scratch[TOT_SCRATCH];

// zero activations (incl. halos) + stats
__global__ void k_zero4(float4* __restrict__ a, int n4, float* __restrict__ st, int nst) {
    int i = blockIdx.x * 256 + threadIdx.x;
    if (i < n4) a[i] = make_float4(0.f, 0.f, 0.f, 0.f);
    if (i < nst) st[i] = 0.f;
}

// masked input into padded x0
__global__ void k_pre(const float* __restrict__ feat, const float* __restrict__ mask,
                      float* __restrict__ x0, float* __restrict__ m0) {
    int v = blockIdx.x * 256 + threadIdx.x;          // 2*64^3
    float m = mask[v] > 0.5f ? 1.f : 0.f;
    m0[v] = m;
    int b = v >> 18, r = v & 262143;
    int z = r >> 12, y = (r >> 6) & 63, x = r & 63;
    int poff = ((z + 1) * 66 + (y + 1)) * 66 + (x + 1);
#pragma unroll
    for (int c = 0; c < 4; c++)
        x0[(b * 4 + c) * 287496 + poff] = feat[(b * 4 + c) * 262144 + r] * m;
}

// all weight transposes fused: wT[(t*CI+ci)*CO+co] = w[(co*CI+ci)*64+t]
__global__ void k_trans_all(const float* __restrict__ w1, const float* __restrict__ w2,
                            const float* __restrict__ w3, const float* __restrict__ tw1,
                            const float* __restrict__ tw2, const float* __restrict__ fw,
                            float* __restrict__ S) {
    int idx = blockIdx.x * 256 + threadIdx.x;
    const float* src; float* dst; int CI, CO, i = idx;
    if (i < 8192)            { src = w1;  dst = S + OW1;  CI = 4;   CO = 32;  }
    else if ((i -= 8192)  < 131072)  { src = w2;  dst = S + OW2;  CI = 32;  CO = 64;  }
    else if ((i -= 131072) < 524288) { src = w3;  dst = S + OW3;  CI = 64;  CO = 128; }
    else if ((i -= 524288) < 1048576){ src = tw1; dst = S + OTW1; CI = 128; CO = 128; }
    else if ((i -= 1048576)< 524288) { src = tw2; dst = S + OTW2; CI = 128; CO = 64;  }
    else if ((i -= 524288) < 2048)   { S[OFW + (i % 64) * 32 + i / 64] = fw[i]; return; }
    else return;
    int t = i & 63, ci = (i >> 6) % CI, co = i / (64 * CI);
    dst[(t * CI + ci) * CO + co] = src[i];
}

// ---------------------------------------------------------------------------
// Mask dilation (+ active count into stats[2*CO])
// ---------------------------------------------------------------------------
template <int DI, int DO>
__global__ void k_maskd_fwd(const float* __restrict__ mi, float* __restrict__ mo,
                            float* __restrict__ cnt) {
    const int DO3 = DO * DO * DO, DI2 = DI * DI, DI3 = DI * DI * DI;
    int v = blockIdx.x * 256 + threadIdx.x;
    int b = v / DO3, r = v % DO3;
    int oz = r / (DO * DO), oy = (r / DO) % DO, ox = r % DO;
    float m = 0.f;
    for (int tz = 0; tz < 4; tz++) {
        int iz = 2 * oz - 1 + tz;
        if ((unsigned)iz >= DI) continue;
        for (int ty = 0; ty < 4; ty++) {
            int iy = 2 * oy - 1 + ty;
            if ((unsigned)iy >= DI) continue;
            const float* p = mi + b * DI3 + iz * DI2 + iy * DI;
            for (int tx = 0; tx < 4; tx++) {
                int ix = 2 * ox - 1 + tx;
                if ((unsigned)ix < DI) m += p[ix];
            }
        }
    }
    float act = m > 0.f ? 1.f : 0.f;
    mo[v] = act;
    float s = act;
    for (int o = 16; o; o >>= 1) s += __shfl_xor_sync(0xffffffffu, s, o);
    if ((threadIdx.x & 31) == 0) atomicAdd(cnt, s);
}

template <int DI, int DO>
__global__ void k_maskd_t(const float* __restrict__ mi, float* __restrict__ mo,
                          float* __restrict__ cnt) {
    const int DO3 = DO * DO * DO, DI2 = DI * DI, DI3 = DI * DI * DI;
    int v = blockIdx.x * 256 + threadIdx.x;
    int b = v / DO3, r = v % DO3;
    int oz = r / (DO * DO), oy = (r / DO) % DO, ox = r % DO;
    int izl[2], iyl[2], ixl[2];
    izl[0] = oz >> 1; izl[1] = (oz & 1) ? (oz >> 1) + 1 : (oz >> 1) - 1;
    iyl[0] = oy >> 1; iyl[1] = (oy & 1) ? (oy >> 1) + 1 : (oy >> 1) - 1;
    ixl[0] = ox >> 1; ixl[1] = (ox & 1) ? (ox >> 1) + 1 : (ox >> 1) - 1;
    float m = 0.f;
#pragma unroll
    for (int jz = 0; jz < 2; jz++) {
        int iz = izl[jz];
        if ((unsigned)iz >= DI) continue;
#pragma unroll
        for (int jy = 0; jy < 2; jy++) {
            int iy = iyl[jy];
            if ((unsigned)iy >= DI) continue;
#pragma unroll
            for (int jx = 0; jx < 2; jx++) {
                int ix = ixl[jx];
                if ((unsigned)ix < DI) m += mi[b * DI3 + iz * DI2 + iy * DI + ix];
            }
        }
    }
    float act = m > 0.f ? 1.f : 0.f;
    mo[v] = act;
    float s = act;
    for (int o = 16; o; o >>= 1) s += __shfl_xor_sync(0xffffffffu, s, o);
    if ((threadIdx.x & 31) == 0) atomicAdd(cnt, s);
}

// ---------------------------------------------------------------------------
// Forward conv k=4 s=2 p=1 on padded input -> padded output. No bounds checks.
// Thread = 1 output voxel x 8 co (4 packed f32x2 accs).
// ---------------------------------------------------------------------------
template <int CI, int CO, int DI, int DO, bool FULLW, int NT>
__global__ void __launch_bounds__(NT) k_conv_fwd(
    const float* __restrict__ x, const float* __restrict__ wT,
    const float* __restrict__ bias, const float* __restrict__ mo,
    float* __restrict__ z, float* __restrict__ stats) {
    constexpr int PI = DI + 2, PO = DO + 2;
    constexpr int PI2 = PI * PI, PI3 = PI * PI * PI, PO3 = PO * PO * PO;
    constexpr int SWSZ = FULLW ? 64 * CI * 8 : 4 * CI * 8;
    __shared__ __align__(16) float sw[SWSZ];
    __shared__ float ssum[8], ssq[8];
    const int DO3 = DO * DO * DO;
    const int co0 = blockIdx.y * 8;
    const int v = blockIdx.x * NT + threadIdx.x;
    const int b = v / DO3, r = v % DO3;
    const int oz = r / (DO * DO), oy = (r / DO) % DO, ox = r % DO;
    u64 acc2[4] = {0ull, 0ull, 0ull, 0ull};

    const float* xorg = x + (b * CI) * PI3 + (2 * oz) * PI2 + (2 * oy) * PI + 2 * ox;

    if (FULLW) {
        for (int i = threadIdx.x; i < 64 * CI * 8; i += NT) {
            int k = i & 7, ci = (i >> 3) % CI, t = i / (8 * CI);
            sw[i] = wT[(t * CI + ci) * CO + co0 + k];
        }
        __syncthreads();
    }

    for (int tz = 0; tz < 4; tz++) {
        for (int ty = 0; ty < 4; ty++) {
            if (!FULLW) {
                __syncthreads();
                for (int i = threadIdx.x; i < 4 * CI * 8; i += NT) {
                    int k = i & 7, ci = (i >> 3) % CI, tx = i / (8 * CI);
                    sw[i] = wT[((tz * 16 + ty * 4 + tx) * CI + ci) * CO + co0 + k];
                }
                __syncthreads();
            }
            const float* xrow = xorg + tz * PI2 + ty * PI;
#pragma unroll
            for (int tx = 0; tx < 4; tx++) {
                const float* xp = xrow + tx;
                const float* wp = FULLW ? sw + (tz * 16 + ty * 4 + tx) * (8 * CI)
                                        : sw + tx * (8 * CI);
#pragma unroll 4
                for (int ci = 0; ci < CI; ci++) {
                    u64 xv = pack2(*xp); xp += PI3;
                    ulonglong2 wa = *reinterpret_cast<const ulonglong2*>(wp);
                    ulonglong2 wb = *reinterpret_cast<const ulonglong2*>(wp + 4);
                    wp += 8;
                    acc2[0] = ffma2(xv, wa.x, acc2[0]);
                    acc2[1] = ffma2(xv, wa.y, acc2[1]);
                    acc2[2] = ffma2(xv, wb.x, acc2[2]);
                    acc2[3] = ffma2(xv, wb.y, acc2[3]);
                }
            }
        }
    }

    const float m2 = mo[v];
    const int poff = ((oz + 1) * PO + (oy + 1)) * PO + (ox + 1);
    float zs[8];
#pragma unroll
    for (int p = 0; p < 4; p++) {
        float2 a = unpack2(acc2[p]);
        float y0 = (a.x + bias[co0 + 2 * p]) * m2;
        float y1 = (a.y + bias[co0 + 2 * p + 1]) * m2;
        zs[2 * p]     = y0 >= 0.f ? y0 : 0.01f * y0;
        zs[2 * p + 1] = y1 >= 0.f ? y1 : 0.01f * y1;
        z[(b * CO + co0 + 2 * p)     * PO3 + poff] = zs[2 * p];
        z[(b * CO + co0 + 2 * p + 1) * PO3 + poff] = zs[2 * p + 1];
    }
    __syncthreads();
    if (threadIdx.x < 8) { ssum[threadIdx.x] = 0.f; ssq[threadIdx.x] = 0.f; }
    __syncthreads();
#pragma unroll
    for (int k = 0; k < 8; k++) {
        float s = zs[k], q = zs[k] * zs[k];
        for (int o = 16; o; o >>= 1) {
            s += __shfl_xor_sync(0xffffffffu, s, o);
            q += __shfl_xor_sync(0xffffffffu, q, o);
        }
        if ((threadIdx.x & 31) == 0) { atomicAdd(&ssum[k], s); atomicAdd(&ssq[k], q); }
    }
    __syncthreads();
    if (threadIdx.x < 8)
        atomicAdd(&stats[co0 + threadIdx.x], ssum[threadIdx.x]);
    else if (threadIdx.x < 16)
        atomicAdd(&stats[CO + co0 + threadIdx.x - 8], ssq[threadIdx.x - 8]);
}

// ---------------------------------------------------------------------------
// Transpose conv via parity classes, padded input, no bounds checks.
// Thread = 1 input voxel x 16 co (8 packed accs). Weights staged per tap.
// ---------------------------------------------------------------------------
template <int CI, int CO, int DI, bool PADOUT>
__global__ void __launch_bounds__(256) k_conv_t(
    const float* __restrict__ x, const float* __restrict__ wT,
    const float* __restrict__ bias, const float* __restrict__ mo,
    float* __restrict__ z, float* __restrict__ stats) {
    constexpr int DO = 2 * DI, PI = DI + 2, PO = DO + 2;
    constexpr int PI2 = PI * PI, PI3 = PI * PI * PI;
    constexpr int DI2 = DI * DI, DI3 = DI * DI * DI, DO3 = DO * DO * DO;
    constexpr int PO3 = PO * PO * PO;
    __shared__ __align__(16) float sw[CI * 16];
    __shared__ float ssum[16], ssq[16];
    const int cls = blockIdx.z;
    const int pz = (cls >> 2) & 1, py = (cls >> 1) & 1, px = cls & 1;
    const int cog = blockIdx.y * 16;
    const int v = blockIdx.x * 256 + threadIdx.x;
    const int b = v / DI3, r = v % DI3;
    const int zi = r / DI2, yi = (r / DI) % DI, xi = r % DI;

    u64 acc2[8];
#pragma unroll
    for (int k = 0; k < 8; k++) acc2[k] = 0ull;

    for (int j = 0; j < 8; j++) {
        const int jz = (j >> 2) & 1, jy = (j >> 1) & 1, jx = j & 1;
        const int tz = pz ? 2 - 2 * jz : 1 + 2 * jz;
        const int ty = py ? 2 - 2 * jy : 1 + 2 * jy;
        const int tx = px ? 2 - 2 * jx : 1 + 2 * jx;
        if (j) __syncthreads();
        for (int i = threadIdx.x; i < CI * 16; i += 256) {
            int k = i & 15, ci = i >> 4;
            sw[i] = wT[((tz * 16 + ty * 4 + tx) * CI + ci) * CO + cog + k];
        }
        __syncthreads();
        const int iz = pz ? zi + jz : zi - jz;
        const int iy = py ? yi + jy : yi - jy;
        const int ix = px ? xi + jx : xi - jx;
        const float* xp = x + (b * CI) * PI3 + (iz + 1) * PI2 + (iy + 1) * PI + (ix + 1);
        const float* wp = sw;
#pragma unroll 4
        for (int ci = 0; ci < CI; ci++) {
            u64 xv = pack2(*xp); xp += PI3;
            ulonglong2 w0 = *reinterpret_cast<const ulonglong2*>(wp);
            ulonglong2 w1 = *reinterpret_cast<const ulonglong2*>(wp + 4);
            ulonglong2 w2 = *reinterpret_cast<const ulonglong2*>(wp + 8);
            ulonglong2 w3 = *reinterpret_cast<const ulonglong2*>(wp + 12);
            wp += 16;
            acc2[0] = ffma2(xv, w0.x, acc2[0]);
            acc2[1] = ffma2(xv, w0.y, acc2[1]);
            acc2[2] = ffma2(xv, w1.x, acc2[2]);
            acc2[3] = ffma2(xv, w1.y, acc2[3]);
            acc2[4] = ffma2(xv, w2.x, acc2[4]);
            acc2[5] = ffma2(xv, w2.y, acc2[5]);
            acc2[6] = ffma2(xv, w3.x, acc2[6]);
            acc2[7] = ffma2(xv, w3.y, acc2[7]);
        }
    }

    const int oz = 2 * zi + pz, oy = 2 * yi + py, ox = 2 * xi + px;
    const int ro = (oz * DO + oy) * DO + ox;
    const float m2 = mo[b * DO3 + ro];
    const int ooff = PADOUT ? ((oz + 1) * PO + (oy + 1)) * PO + (ox + 1) : ro;
    const int ostr = PADOUT ? PO3 : DO3;
    float zs[16];
#pragma unroll
    for (int p = 0; p < 8; p++) {
        float2 a = unpack2(acc2[p]);
        float y0 = (a.x + bias[cog + 2 * p]) * m2;
        float y1 = (a.y + bias[cog + 2 * p + 1]) * m2;
        zs[2 * p]     = y0 >= 0.f ? y0 : 0.01f * y0;
        zs[2 * p + 1] = y1 >= 0.f ? y1 : 0.01f * y1;
        z[(b * CO + cog + 2 * p)     * ostr + ooff] = zs[2 * p];
        z[(b * CO + cog + 2 * p + 1) * ostr + ooff] = zs[2 * p + 1];
    }
    __syncthreads();
    if (threadIdx.x < 16) { ssum[threadIdx.x] = 0.f; ssq[threadIdx.x] = 0.f; }
    __syncthreads();
#pragma unroll
    for (int k = 0; k < 16; k++) {
        float s = zs[k], q = zs[k] * zs[k];
        for (int o = 16; o; o >>= 1) {
            s += __shfl_xor_sync(0xffffffffu, s, o);
            q += __shfl_xor_sync(0xffffffffu, q, o);
        }
        if ((threadIdx.x & 31) == 0) { atomicAdd(&ssum[k], s); atomicAdd(&ssq[k], q); }
    }
    __syncthreads();
    if (threadIdx.x < 16)
        atomicAdd(&stats[cog + threadIdx.x], ssum[threadIdx.x]);
    else if (threadIdx.x < 32)
        atomicAdd(&stats[CO + cog + threadIdx.x - 16], ssq[threadIdx.x - 16]);
}

// ---------------------------------------------------------------------------
// BN apply with inline finalize (each block recomputes scale/shift from stats)
// ---------------------------------------------------------------------------
__global__ void k_norm(float* __restrict__ z, const float* __restrict__ mo,
                       const float* __restrict__ stats, const float* __restrict__ g,
                       const float* __restrict__ be, int CO, int D, int pd) {
    __shared__ float sc[128], sh[128];
    if (threadIdx.x < CO) {
        int c = threadIdx.x;
        float cnt  = fmaxf(stats[2 * CO], 1.f);
        float mean = stats[c] / cnt;
        float var  = stats[CO + c] / cnt - mean * mean;
        float s = g[c] * rsqrtf(var + 1e-5f);
        sc[c] = s;
        sh[c] = be[c] - mean * s;
    }
    __syncthreads();
    const int D3 = D * D * D, P = D + 2 * pd, P3 = P * P * P;
    int idx = blockIdx.x * 256 + threadIdx.x;
    int c = (idx / D3) % CO, b = idx / (D3 * CO), r = idx % D3;
    int rz = r / (D * D), ry = (r / D) % D, rx = r % D;
    int off = (b * CO + c) * P3 + ((rz + pd) * P + (ry + pd)) * P + (rx + pd);
    z[off] = fmaf(z[off], sc[c], sh[c]) * mo[b * D3 + r];
}

// ---------------------------------------------------------------------------
// Head: dense 1x1x1 conv 64->32 on unpadded z5
// ---------------------------------------------------------------------------
__global__ void __launch_bounds__(256) k_head(const float* __restrict__ x,
                                              const float* __restrict__ fwT,
                                              const float* __restrict__ fb,
                                              float* __restrict__ out) {
    __shared__ __align__(16) float sw[64 * 32];
    for (int i = threadIdx.x; i < 2048; i += 256) sw[i] = fwT[i];
    __syncthreads();
    const int D3 = 32768;
    int v = blockIdx.x * 256 + threadIdx.x;
    int b = v / D3, r = v % D3;
    u64 acc2[16];
#pragma unroll
    for (int k = 0; k < 16; k++) acc2[k] = 0ull;
    const float* xp = x + b * 64 * D3 + r;
#pragma unroll 8
    for (int ci = 0; ci < 64; ci++) {
        u64 xv = pack2(*xp); xp += D3;
        const ulonglong2* w2 = reinterpret_cast<const ulonglong2*>(sw + ci * 32);
#pragma unroll
        for (int q = 0; q < 8; q++) {
            ulonglong2 w = w2[q];
            acc2[2 * q]     = ffma2(xv, w.x, acc2[2 * q]);
            acc2[2 * q + 1] = ffma2(xv, w.y, acc2[2 * q + 1]);
        }
    }
#pragma unroll
    for (int k = 0; k < 16; k++) {
        float2 a = unpack2(acc2[k]);
        out[(b * 32 + 2 * k)     * D3 + r] = a.x + fb[2 * k];
        out[(b * 32 + 2 * k + 1) * D3 + r] = a.y + fb[2 * k + 1];
    }
}

// ---------------------------------------------------------------------------
// Host launcher
// ---------------------------------------------------------------------------
extern "C" void kernel_launch(void* const* d_in, const int* in_sizes, int n_in,
                              void* d_out, int out_size) {
    (void)in_sizes; (void)n_in; (void)out_size;
    float* S = nullptr;
    cudaGetSymbolAddress((void**)&S, g_scratch);

    const float* feat = (const float*)d_in[0];
    const float* mask = (const float*)d_in[1];
    const float* w1  = (const float*)d_in[2];  const float* b1  = (const float*)d_in[3];
    const float* g1  = (const float*)d_in[4];  const float* be1 = (const float*)d_in[5];
    const float* w2  = (const float*)d_in[6];  const float* b2  = (const float*)d_in[7];
    const float* g2  = (const float*)d_in[8];  const float* be2 = (const float*)d_in[9];
    const float* w3  = (const float*)d_in[10]; const float* b3  = (const float*)d_in[11];
    const float* g3  = (const float*)d_in[12]; const float* be3 = (const float*)d_in[13];
    const float* tw1 = (const float*)d_in[14]; const float* tb1 = (const float*)d_in[15];
    const float* tg1 = (const float*)d_in[16]; const float* tbe1= (const float*)d_in[17];
    const float* tw2 = (const float*)d_in[18]; const float* tb2 = (const float*)d_in[19];
    const float* tg2 = (const float*)d_in[20]; const float* tbe2= (const float*)d_in[21];
    const float* fw  = (const float*)d_in[22]; const float* fb  = (const float*)d_in[23];
    float* out = (float*)d_out;

    float *x0 = S+OX0, *z1 = S+OZ1, *z2 = S+OZ2, *z3 = S+OZ3, *z4 = S+OZ4, *z5 = S+OZ5;
    float *m0 = S+OM0, *m1 = S+OM1, *m2 = S+OM2, *m3 = S+OM3, *m4 = S+OM4, *m5 = S+OM5;
    float *w1T = S+OW1, *w2T = S+OW2, *w3T = S+OW3, *tw1T = S+OTW1, *tw2T = S+OTW2, *fwT = S+OFW;
    float *st = S+OST;

    // launches 0..4 (prep), so ncu -s 5 -c 1 profiles conv1
    k_zero4<<<7140, 256>>>((float4*)S, 7310912 / 4, st, 5 * 260);
    k_trans_all<<<8744, 256>>>(w1, w2, w3, tw1, tw2, fw, S);
    k_pre<<<2048, 256>>>(feat, mask, x0, m0);
    k_maskd_fwd<64, 32><<<256, 256>>>(m0, m1, st + 0 * 260 + 64);
    k_maskd_fwd<32, 16><<<32, 256>>>(m1, m2, st + 1 * 260 + 128);

    // stage 1: 4 -> 32, 64^3 -> 32^3
    k_conv_fwd<4, 32, 64, 32, true, 256><<<dim3(256, 4), 256>>>(x0, w1T, b1, m1, z1, st + 0 * 260);
    k_norm<<<8192, 256>>>(z1, m1, st + 0 * 260, g1, be1, 32, 32, 1);

    // stage 2: 32 -> 64, 32^3 -> 16^3
    k_conv_fwd<32, 64, 32, 16, false, 256><<<dim3(32, 8), 256>>>(z1, w2T, b2, m2, z2, st + 1 * 260);
    k_maskd_fwd<16, 8><<<4, 256>>>(m2, m3, st + 2 * 260 + 256);
    k_norm<<<2048, 256>>>(z2, m2, st + 1 * 260, g2, be2, 64, 16, 1);

    // stage 3: 64 -> 128, 16^3 -> 8^3
    k_conv_fwd<64, 128, 16, 8, false, 128><<<dim3(8, 16), 128>>>(z2, w3T, b3, m3, z3, st + 2 * 260);
    k_norm<<<512, 256>>>(z3, m3, st + 2 * 260, g3, be3, 128, 8, 1);

    // stage 4: tconv 128 -> 128, 8^3 -> 16^3 (padded out)
    k_maskd_t<8, 16><<<32, 256>>>(m3, m4, st + 3 * 260 + 256);
    k_conv_t<128, 128, 8, true><<<dim3(4, 8, 8), 256>>>(z3, tw1T, tb1, m4, z4, st + 3 * 260);
    k_norm<<<4096, 256>>>(z4, m4, st + 3 * 260, tg1, tbe1, 128, 16, 1);

    // stage 5: tconv 128 -> 64, 16^3 -> 32^3 (unpadded out)
    k_maskd_t<16, 32><<<256, 256>>>(m4, m5, st + 4 * 260 + 128);
    k_conv_t<128, 64, 16, false><<<dim3(32, 4, 8), 256>>>(z4, tw2T, tb2, m5, z5, st + 4 * 260);
    k_norm<<<16384, 256>>>(z5, m5, st + 4 * 260, tg2, tbe2, 64, 32, 0);

    // head
    k_head<<<256, 256>>>(z5, fwT, fb, out);
}

// round 6
// speedup vs baseline: 1.0666x; 1.0666x over previous
#include <cuda_runtime.h>
#include <math.h>

typedef unsigned long long u64;

__device__ __forceinline__ u64 pack2(float v) {
    u64 r; asm("mov.b64 %0, {%1, %1};" : "=l"(r) : "f"(v)); return r;
}
__device__ __forceinline__ u64 ffma2(u64 a, u64 b, u64 c) {
    u64 d; asm("fma.rn.f32x2 %0, %1, %2, %3;" : "=l"(d) : "l"(a), "l"(b), "l"(c)); return d;
}
__device__ __forceinline__ float2 unpack2(u64 a) {
    float2 f; asm("mov.b64 {%0, %1}, %2;" : "=f"(f.x), "=f"(f.y) : "l"(a)); return f;
}

// ---------------------------------------------------------------------------
// Scratch arena. Activations halo-padded: dim D stored as P=D+2, interior
// voxel (z,y,x) at ((z+1)*P+(y+1))*P+(x+1).
// ---------------------------------------------------------------------------
constexpr int OX0  = 0;          // 2*4*66^3   = 2299968
constexpr int OZ1  = 2299968;    // 2*32*34^3  = 2515456
constexpr int OZ2  = 4815424;    // 2*64*18^3  = 746496
constexpr int OZ3  = 5561920;    // 2*128*10^3 = 256000
constexpr int OZ4  = 5817920;    // 2*128*18^3 = 1492992
constexpr int OZ5  = 7310912;    // 2*64*32^3  = 4194304 (unpadded)
constexpr int OM0  = 11505216;   // 2*64^3
constexpr int OM1  = 12029504;   // 2*32^3
constexpr int OM2  = 12095040;   // 2*16^3
constexpr int OM3  = 12103232;   // 2*8^3
constexpr int OM4  = 12104256;   // 2*16^3
constexpr int OM5  = 12112448;   // 2*32^3
constexpr int OW1  = 12177984;   // 8192
constexpr int OW2  = 12186176;   // 131072
constexpr int OW3  = 12317248;   // 524288
constexpr int OTW1 = 12841536;   // 1048576
constexpr int OTW2 = 13890112;   // 524288
constexpr int OFW  = 14414400;   // 2048
constexpr int OST  = 14416448;   // 5*260
constexpr int TOT_SCRATCH = 14417920;

__device__ __align__(16) float g_scratch[TOT_SCRATCH];

__global__ void k_zero4(float4* __restrict__ a, int n4, float* __restrict__ st, int nst) {
    int i = blockIdx.x * 256 + threadIdx.x;
    if (i < n4) a[i] = make_float4(0.f, 0.f, 0.f, 0.f);
    if (i < nst) st[i] = 0.f;
}

__global__ void k_pre(const float* __restrict__ feat, const float* __restrict__ mask,
                      float* __restrict__ x0, float* __restrict__ m0) {
    int v = blockIdx.x * 256 + threadIdx.x;
    float m = mask[v] > 0.5f ? 1.f : 0.f;
    m0[v] = m;
    int b = v >> 18, r = v & 262143;
    int z = r >> 12, y = (r >> 6) & 63, x = r & 63;
    int poff = ((z + 1) * 66 + (y + 1)) * 66 + (x + 1);
#pragma unroll
    for (int c = 0; c < 4; c++)
        x0[(b * 4 + c) * 287496 + poff] = feat[(b * 4 + c) * 262144 + r] * m;
}

__global__ void k_trans_all(const float* __restrict__ w1, const float* __restrict__ w2,
                            const float* __restrict__ w3, const float* __restrict__ tw1,
                            const float* __restrict__ tw2, const float* __restrict__ fw,
                            float* __restrict__ S) {
    int idx = blockIdx.x * 256 + threadIdx.x;
    const float* src; float* dst; int CI, CO, i = idx;
    if (i < 8192)            { src = w1;  dst = S + OW1;  CI = 4;   CO = 32;  }
    else if ((i -= 8192)  < 131072)  { src = w2;  dst = S + OW2;  CI = 32;  CO = 64;  }
    else if ((i -= 131072) < 524288) { src = w3;  dst = S + OW3;  CI = 64;  CO = 128; }
    else if ((i -= 524288) < 1048576){ src = tw1; dst = S + OTW1; CI = 128; CO = 128; }
    else if ((i -= 1048576)< 524288) { src = tw2; dst = S + OTW2; CI = 128; CO = 64;  }
    else if ((i -= 524288) < 2048)   { S[OFW + (i % 64) * 32 + i / 64] = fw[i]; return; }
    else return;
    int t = i & 63, ci = (i >> 6) % CI, co = i / (64 * CI);
    dst[(t * CI + ci) * CO + co] = src[i];
}

// ---------------------------------------------------------------------------
// Mask dilation (+ active count into stats[2*CO])
// ---------------------------------------------------------------------------
template <int DI, int DO>
__global__ void k_maskd_fwd(const float* __restrict__ mi, float* __restrict__ mo,
                            float* __restrict__ cnt) {
    const int DO3 = DO * DO * DO, DI2 = DI * DI, DI3 = DI * DI * DI;
    int v = blockIdx.x * 256 + threadIdx.x;
    int b = v / DO3, r = v % DO3;
    int oz = r / (DO * DO), oy = (r / DO) % DO, ox = r % DO;
    float m = 0.f;
    for (int tz = 0; tz < 4; tz++) {
        int iz = 2 * oz - 1 + tz;
        if ((unsigned)iz >= DI) continue;
        for (int ty = 0; ty < 4; ty++) {
            int iy = 2 * oy - 1 + ty;
            if ((unsigned)iy >= DI) continue;
            const float* p = mi + b * DI3 + iz * DI2 + iy * DI;
            for (int tx = 0; tx < 4; tx++) {
                int ix = 2 * ox - 1 + tx;
                if ((unsigned)ix < DI) m += p[ix];
            }
        }
    }
    float act = m > 0.f ? 1.f : 0.f;
    mo[v] = act;
    float s = act;
    for (int o = 16; o; o >>= 1) s += __shfl_xor_sync(0xffffffffu, s, o);
    if ((threadIdx.x & 31) == 0) atomicAdd(cnt, s);
}

template <int DI, int DO>
__global__ void k_maskd_t(const float* __restrict__ mi, float* __restrict__ mo,
                          float* __restrict__ cnt) {
    const int DO3 = DO * DO * DO, DI2 = DI * DI, DI3 = DI * DI * DI;
    int v = blockIdx.x * 256 + threadIdx.x;
    int b = v / DO3, r = v % DO3;
    int oz = r / (DO * DO), oy = (r / DO) % DO, ox = r % DO;
    int izl[2], iyl[2], ixl[2];
    izl[0] = oz >> 1; izl[1] = (oz & 1) ? (oz >> 1) + 1 : (oz >> 1) - 1;
    iyl[0] = oy >> 1; iyl[1] = (oy & 1) ? (oy >> 1) + 1 : (oy >> 1) - 1;
    ixl[0] = ox >> 1; ixl[1] = (ox & 1) ? (ox >> 1) + 1 : (ox >> 1) - 1;
    float m = 0.f;
#pragma unroll
    for (int jz = 0; jz < 2; jz++) {
        int iz = izl[jz];
        if ((unsigned)iz >= DI) continue;
#pragma unroll
        for (int jy = 0; jy < 2; jy++) {
            int iy = iyl[jy];
            if ((unsigned)iy >= DI) continue;
#pragma unroll
            for (int jx = 0; jx < 2; jx++) {
                int ix = ixl[jx];
                if ((unsigned)ix < DI) m += mi[b * DI3 + iz * DI2 + iy * DI + ix];
            }
        }
    }
    float act = m > 0.f ? 1.f : 0.f;
    mo[v] = act;
    float s = act;
    for (int o = 16; o; o >>= 1) s += __shfl_xor_sync(0xffffffffu, s, o);
    if ((threadIdx.x & 31) == 0) atomicAdd(cnt, s);
}

// ---------------------------------------------------------------------------
// Forward conv, 1 voxel x 8 co (used for conv1 FULLW and conv3).
// ---------------------------------------------------------------------------
template <int CI, int CO, int DI, int DO, bool FULLW, int NT>
__global__ void __launch_bounds__(NT) k_conv_fwd(
    const float* __restrict__ x, const float* __restrict__ wT,
    const float* __restrict__ bias, const float* __restrict__ mo,
    float* __restrict__ z, float* __restrict__ stats) {
    constexpr int PI = DI + 2, PO = DO + 2;
    constexpr int PI2 = PI * PI, PI3 = PI * PI * PI, PO3 = PO * PO * PO;
    constexpr int SWSZ = FULLW ? 64 * CI * 8 : 4 * CI * 8;
    __shared__ __align__(16) float sw[SWSZ];
    __shared__ float ssum[8], ssq[8];
    const int DO3 = DO * DO * DO;
    const int co0 = blockIdx.y * 8;
    const int v = blockIdx.x * NT + threadIdx.x;
    const int b = v / DO3, r = v % DO3;
    const int oz = r / (DO * DO), oy = (r / DO) % DO, ox = r % DO;
    u64 acc2[4] = {0ull, 0ull, 0ull, 0ull};

    const float* xorg = x + (b * CI) * PI3 + (2 * oz) * PI2 + (2 * oy) * PI + 2 * ox;

    if (FULLW) {
        for (int i = threadIdx.x; i < 64 * CI * 8; i += NT) {
            int k = i & 7, ci = (i >> 3) % CI, t = i / (8 * CI);
            sw[i] = wT[(t * CI + ci) * CO + co0 + k];
        }
        __syncthreads();
    }

    for (int tz = 0; tz < 4; tz++) {
        for (int ty = 0; ty < 4; ty++) {
            if (!FULLW) {
                __syncthreads();
                for (int i = threadIdx.x; i < 4 * CI * 8; i += NT) {
                    int k = i & 7, ci = (i >> 3) % CI, tx = i / (8 * CI);
                    sw[i] = wT[((tz * 16 + ty * 4 + tx) * CI + ci) * CO + co0 + k];
                }
                __syncthreads();
            }
            const float* xrow = xorg + tz * PI2 + ty * PI;
#pragma unroll
            for (int tx = 0; tx < 4; tx++) {
                const float* xp = xrow + tx;
                const float* wp = FULLW ? sw + (tz * 16 + ty * 4 + tx) * (8 * CI)
                                        : sw + tx * (8 * CI);
#pragma unroll 4
                for (int ci = 0; ci < CI; ci++) {
                    u64 xv = pack2(*xp); xp += PI3;
                    ulonglong2 wa = *reinterpret_cast<const ulonglong2*>(wp);
                    ulonglong2 wb = *reinterpret_cast<const ulonglong2*>(wp + 4);
                    wp += 8;
                    acc2[0] = ffma2(xv, wa.x, acc2[0]);
                    acc2[1] = ffma2(xv, wa.y, acc2[1]);
                    acc2[2] = ffma2(xv, wb.x, acc2[2]);
                    acc2[3] = ffma2(xv, wb.y, acc2[3]);
                }
            }
        }
    }

    const float m2 = mo[v];
    const int poff = ((oz + 1) * PO + (oy + 1)) * PO + (ox + 1);
    float zs[8];
#pragma unroll
    for (int p = 0; p < 4; p++) {
        float2 a = unpack2(acc2[p]);
        float y0 = (a.x + bias[co0 + 2 * p]) * m2;
        float y1 = (a.y + bias[co0 + 2 * p + 1]) * m2;
        zs[2 * p]     = y0 >= 0.f ? y0 : 0.01f * y0;
        zs[2 * p + 1] = y1 >= 0.f ? y1 : 0.01f * y1;
        z[(b * CO + co0 + 2 * p)     * PO3 + poff] = zs[2 * p];
        z[(b * CO + co0 + 2 * p + 1) * PO3 + poff] = zs[2 * p + 1];
    }
    __syncthreads();
    if (threadIdx.x < 8) { ssum[threadIdx.x] = 0.f; ssq[threadIdx.x] = 0.f; }
    __syncthreads();
#pragma unroll
    for (int k = 0; k < 8; k++) {
        float s = zs[k], q = zs[k] * zs[k];
        for (int o = 16; o; o >>= 1) {
            s += __shfl_xor_sync(0xffffffffu, s, o);
            q += __shfl_xor_sync(0xffffffffu, q, o);
        }
        if ((threadIdx.x & 31) == 0) { atomicAdd(&ssum[k], s); atomicAdd(&ssq[k], q); }
    }
    __syncthreads();
    if (threadIdx.x < 8)
        atomicAdd(&stats[co0 + threadIdx.x], ssum[threadIdx.x]);
    else if (threadIdx.x < 16)
        atomicAdd(&stats[CO + co0 + threadIdx.x - 8], ssq[threadIdx.x - 8]);
}

// ---------------------------------------------------------------------------
// Forward conv, 2 adjacent output voxels (ox even, ox+1) x 8 co per thread.
// The 2 voxels' 4 x-taps are covered by 6 consecutive floats = 3 LDG.64.
// Weights staged per tz (16 taps).
// ---------------------------------------------------------------------------
template <int CI, int CO, int DI, int DO>
__global__ void __launch_bounds__(256) k_conv_fwd2(
    const float* __restrict__ x, const float* __restrict__ wT,
    const float* __restrict__ bias, const float* __restrict__ mo,
    float* __restrict__ z, float* __restrict__ stats) {
    constexpr int PI = DI + 2, PO = DO + 2;
    constexpr int PI2 = PI * PI, PI3 = PI2 * PI, PO3 = PO * PO * PO;
    constexpr int DO3 = DO * DO * DO, HDO3 = DO3 / 2;
    __shared__ __align__(16) float sw[16 * CI * 8];
    __shared__ float ssum[8], ssq[8];
    const int co0 = blockIdx.y * 8;
    const int v = blockIdx.x * 256 + threadIdx.x;
    const int b = v / HDO3, rp = v % HDO3;
    const int r = 2 * rp;
    const int oz = r / (DO * DO), oy = (r / DO) % DO, ox = r % DO;   // ox even
    u64 aA[4] = {0ull,0ull,0ull,0ull}, aB[4] = {0ull,0ull,0ull,0ull};
    const float* xbase = x + (b * CI) * PI3 + (2 * oz) * PI2 + (2 * oy) * PI + 2 * ox;

    for (int tz = 0; tz < 4; tz++) {
        __syncthreads();
        for (int i = threadIdx.x; i < 16 * CI * 8; i += 256) {
            int k = i & 7, ci = (i >> 3) % CI, s = i / (8 * CI);
            sw[i] = wT[((tz * 16 + s) * CI + ci) * CO + co0 + k];
        }
        __syncthreads();
        for (int ty = 0; ty < 4; ty++) {
            const float* xr = xbase + tz * PI2 + ty * PI;
#pragma unroll 4
            for (int ci = 0; ci < CI; ci++) {
                const float* xp = xr + ci * PI3;
                float2 x01 = *reinterpret_cast<const float2*>(xp);
                float2 x23 = *reinterpret_cast<const float2*>(xp + 2);
                float2 x45 = *reinterpret_cast<const float2*>(xp + 4);
                u64 p[6];
                p[0] = pack2(x01.x); p[1] = pack2(x01.y); p[2] = pack2(x23.x);
                p[3] = pack2(x23.y); p[4] = pack2(x45.x); p[5] = pack2(x45.y);
#pragma unroll
                for (int tx = 0; tx < 4; tx++) {
                    const float* wp = sw + ((ty * 4 + tx) * CI + ci) * 8;
                    ulonglong2 w0 = *reinterpret_cast<const ulonglong2*>(wp);
                    ulonglong2 w1 = *reinterpret_cast<const ulonglong2*>(wp + 4);
                    aA[0] = ffma2(p[tx], w0.x, aA[0]);
                    aA[1] = ffma2(p[tx], w0.y, aA[1]);
                    aA[2] = ffma2(p[tx], w1.x, aA[2]);
                    aA[3] = ffma2(p[tx], w1.y, aA[3]);
                    aB[0] = ffma2(p[tx + 2], w0.x, aB[0]);
                    aB[1] = ffma2(p[tx + 2], w0.y, aB[1]);
                    aB[2] = ffma2(p[tx + 2], w1.x, aB[2]);
                    aB[3] = ffma2(p[tx + 2], w1.y, aB[3]);
                }
            }
        }
    }

    const float mA = mo[b * DO3 + r], mB = mo[b * DO3 + r + 1];
    const int poffA = ((oz + 1) * PO + (oy + 1)) * PO + (ox + 1);
    float zsA[8], zsB[8];
#pragma unroll
    for (int p = 0; p < 4; p++) {
        float2 a = unpack2(aA[p]);
        float2 bb = unpack2(aB[p]);
        float bi0 = bias[co0 + 2 * p], bi1 = bias[co0 + 2 * p + 1];
        float yA0 = (a.x + bi0) * mA, yA1 = (a.y + bi1) * mA;
        float yB0 = (bb.x + bi0) * mB, yB1 = (bb.y + bi1) * mB;
        zsA[2*p]   = yA0 >= 0.f ? yA0 : 0.01f * yA0;
        zsA[2*p+1] = yA1 >= 0.f ? yA1 : 0.01f * yA1;
        zsB[2*p]   = yB0 >= 0.f ? yB0 : 0.01f * yB0;
        zsB[2*p+1] = yB1 >= 0.f ? yB1 : 0.01f * yB1;
        float* zp0 = z + (b * CO + co0 + 2 * p) * PO3 + poffA;
        float* zp1 = z + (b * CO + co0 + 2 * p + 1) * PO3 + poffA;
        zp0[0] = zsA[2*p];   zp0[1] = zsB[2*p];
        zp1[0] = zsA[2*p+1]; zp1[1] = zsB[2*p+1];
    }
    __syncthreads();
    if (threadIdx.x < 8) { ssum[threadIdx.x] = 0.f; ssq[threadIdx.x] = 0.f; }
    __syncthreads();
#pragma unroll
    for (int k = 0; k < 8; k++) {
        float s = zsA[k] + zsB[k];
        float q = zsA[k] * zsA[k] + zsB[k] * zsB[k];
        for (int o = 16; o; o >>= 1) {
            s += __shfl_xor_sync(0xffffffffu, s, o);
            q += __shfl_xor_sync(0xffffffffu, q, o);
        }
        if ((threadIdx.x & 31) == 0) { atomicAdd(&ssum[k], s); atomicAdd(&ssq[k], q); }
    }
    __syncthreads();
    if (threadIdx.x < 8)
        atomicAdd(&stats[co0 + threadIdx.x], ssum[threadIdx.x]);
    else if (threadIdx.x < 16)
        atomicAdd(&stats[CO + co0 + threadIdx.x - 8], ssq[threadIdx.x - 8]);
}

// ---------------------------------------------------------------------------
// Transpose conv, 2 adjacent input voxels (xi even, xi+1) x 16 co per thread.
// Per (jz,jy) pair both jx taps of both voxels read 3 consecutive floats.
// Weights staged per (jz,jy): 2 taps x CI x 16 co.
// ---------------------------------------------------------------------------
template <int CI, int CO, int DI, bool PADOUT>
__global__ void __launch_bounds__(256) k_conv_t2(
    const float* __restrict__ x, const float* __restrict__ wT,
    const float* __restrict__ bias, const float* __restrict__ mo,
    float* __restrict__ z, float* __restrict__ stats) {
    constexpr int DO = 2 * DI, PI = DI + 2, PO = DO + 2;
    constexpr int PI2 = PI * PI, PI3 = PI2 * PI;
    constexpr int DI2 = DI * DI, DI3 = DI2 * DI, DO3 = DO * DO * DO;
    constexpr int PO3 = PO * PO * PO, HDI3 = DI3 / 2;
    __shared__ __align__(16) float sw[2 * CI * 16];
    __shared__ float ssum[16], ssq[16];
    const int cls = blockIdx.z;
    const int pz = (cls >> 2) & 1, py = (cls >> 1) & 1, px = cls & 1;
    const int cog = blockIdx.y * 16;
    const int v = blockIdx.x * 256 + threadIdx.x;
    const int b = v / HDI3, rp = v % HDI3;
    const int r = 2 * rp;
    const int zi = r / DI2, yi = (r / DI) % DI, xi = r % DI;   // xi even

    u64 aA[8], aB[8];
#pragma unroll
    for (int k = 0; k < 8; k++) { aA[k] = 0ull; aB[k] = 0ull; }

    // padded x offset of the first of 3 consecutive floats
    const int sxp = (px ? xi : xi - 1) + 1;

    for (int jp = 0; jp < 4; jp++) {
        const int jz = jp >> 1, jy = jp & 1;
        const int tz = pz ? 2 - 2 * jz : 1 + 2 * jz;
        const int ty = py ? 2 - 2 * jy : 1 + 2 * jy;
        if (jp) __syncthreads();
        for (int i = threadIdx.x; i < 2 * CI * 16; i += 256) {
            int k = i & 15, ci = (i >> 4) % CI, jx = i / (16 * CI);
            int tx = px ? 2 - 2 * jx : 1 + 2 * jx;
            sw[i] = wT[((tz * 16 + ty * 4 + tx) * CI + ci) * CO + cog + k];
        }
        __syncthreads();
        const int iz = pz ? zi + jz : zi - jz;
        const int iy = py ? yi + jy : yi - jy;
        const float* xr = x + (b * CI) * PI3 + (iz + 1) * PI2 + (iy + 1) * PI + sxp;
#pragma unroll 2
        for (int ci = 0; ci < CI; ci++) {
            const float* xp = xr + ci * PI3;
            u64 p0 = pack2(xp[0]), p1 = pack2(xp[1]), p2 = pack2(xp[2]);
            // jx = 0: voxel A uses px?p0:p1, voxel B uses px?p1:p2
            {
                const float* wp = sw + ci * 16;
                ulonglong2 w0 = *reinterpret_cast<const ulonglong2*>(wp);
                ulonglong2 w1 = *reinterpret_cast<const ulonglong2*>(wp + 4);
                ulonglong2 w2 = *reinterpret_cast<const ulonglong2*>(wp + 8);
                ulonglong2 w3 = *reinterpret_cast<const ulonglong2*>(wp + 12);
                u64 xA = px ? p0 : p1;
                u64 xB = px ? p1 : p2;
                aA[0] = ffma2(xA, w0.x, aA[0]); aA[1] = ffma2(xA, w0.y, aA[1]);
                aA[2] = ffma2(xA, w1.x, aA[2]); aA[3] = ffma2(xA, w1.y, aA[3]);
                aA[4] = ffma2(xA, w2.x, aA[4]); aA[5] = ffma2(xA, w2.y, aA[5]);
                aA[6] = ffma2(xA, w3.x, aA[6]); aA[7] = ffma2(xA, w3.y, aA[7]);
                aB[0] = ffma2(xB, w0.x, aB[0]); aB[1] = ffma2(xB, w0.y, aB[1]);
                aB[2] = ffma2(xB, w1.x, aB[2]); aB[3] = ffma2(xB, w1.y, aB[3]);
                aB[4] = ffma2(xB, w2.x, aB[4]); aB[5] = ffma2(xB, w2.y, aB[5]);
                aB[6] = ffma2(xB, w3.x, aB[6]); aB[7] = ffma2(xB, w3.y, aB[7]);
            }
            // jx = 1: voxel A uses px?p1:p0, voxel B uses px?p2:p1
            {
                const float* wp = sw + (CI + ci) * 16;
                ulonglong2 w0 = *reinterpret_cast<const ulonglong2*>(wp);
                ulonglong2 w1 = *reinterpret_cast<const ulonglong2*>(wp + 4);
                ulonglong2 w2 = *reinterpret_cast<const ulonglong2*>(wp + 8);
                ulonglong2 w3 = *reinterpret_cast<const ulonglong2*>(wp + 12);
                u64 xA = px ? p1 : p0;
                u64 xB = px ? p2 : p1;
                aA[0] = ffma2(xA, w0.x, aA[0]); aA[1] = ffma2(xA, w0.y, aA[1]);
                aA[2] = ffma2(xA, w1.x, aA[2]); aA[3] = ffma2(xA, w1.y, aA[3]);
                aA[4] = ffma2(xA, w2.x, aA[4]); aA[5] = ffma2(xA, w2.y, aA[5]);
                aA[6] = ffma2(xA, w3.x, aA[6]); aA[7] = ffma2(xA, w3.y, aA[7]);
                aB[0] = ffma2(xB, w0.x, aB[0]); aB[1] = ffma2(xB, w0.y, aB[1]);
                aB[2] = ffma2(xB, w1.x, aB[2]); aB[3] = ffma2(xB, w1.y, aB[3]);
                aB[4] = ffma2(xB, w2.x, aB[4]); aB[5] = ffma2(xB, w2.y, aB[5]);
                aB[6] = ffma2(xB, w3.x, aB[6]); aB[7] = ffma2(xB, w3.y, aB[7]);
            }
        }
    }

    const int oz = 2 * zi + pz, oy = 2 * yi + py;
    const int oxA = 2 * xi + px;
    const int roA = (oz * DO + oy) * DO + oxA;      // voxel B at roA + 2
    const float mA = mo[b * DO3 + roA], mB = mo[b * DO3 + roA + 2];
    const int ooffA = PADOUT ? ((oz + 1) * PO + (oy + 1)) * PO + (oxA + 1) : roA;
    const int ostr  = PADOUT ? PO3 : DO3;
    float zsA[16], zsB[16];
#pragma unroll
    for (int p = 0; p < 8; p++) {
        float2 a = unpack2(aA[p]);
        float2 bb = unpack2(aB[p]);
        float bi0 = bias[cog + 2 * p], bi1 = bias[cog + 2 * p + 1];
        float yA0 = (a.x + bi0) * mA, yA1 = (a.y + bi1) * mA;
        float yB0 = (bb.x + bi0) * mB, yB1 = (bb.y + bi1) * mB;
        zsA[2*p]   = yA0 >= 0.f ? yA0 : 0.01f * yA0;
        zsA[2*p+1] = yA1 >= 0.f ? yA1 : 0.01f * yA1;
        zsB[2*p]   = yB0 >= 0.f ? yB0 : 0.01f * yB0;
        zsB[2*p+1] = yB1 >= 0.f ? yB1 : 0.01f * yB1;
        float* zp0 = z + (b * CO + cog + 2 * p) * ostr + ooffA;
        float* zp1 = z + (b * CO + cog + 2 * p + 1) * ostr + ooffA;
        zp0[0] = zsA[2*p];   zp0[2] = zsB[2*p];
        zp1[0] = zsA[2*p+1]; zp1[2] = zsB[2*p+1];
    }
    __syncthreads();
    if (threadIdx.x < 16) { ssum[threadIdx.x] = 0.f; ssq[threadIdx.x] = 0.f; }
    __syncthreads();
#pragma unroll
    for (int k = 0; k < 16; k++) {
        float s = zsA[k] + zsB[k];
        float q = zsA[k] * zsA[k] + zsB[k] * zsB[k];
        for (int o = 16; o; o >>= 1) {
            s += __shfl_xor_sync(0xffffffffu, s, o);
            q += __shfl_xor_sync(0xffffffffu, q, o);
        }
        if ((threadIdx.x & 31) == 0) { atomicAdd(&ssum[k], s); atomicAdd(&ssq[k], q); }
    }
    __syncthreads();
    if (threadIdx.x < 16)
        atomicAdd(&stats[cog + threadIdx.x], ssum[threadIdx.x]);
    else if (threadIdx.x < 32)
        atomicAdd(&stats[CO + cog + threadIdx.x - 16], ssq[threadIdx.x - 16]);
}

// ---------------------------------------------------------------------------
// BN apply with inline finalize
// ---------------------------------------------------------------------------
__global__ void k_norm(float* __restrict__ z, const float* __restrict__ mo,
                       const float* __restrict__ stats, const float* __restrict__ g,
                       const float* __restrict__ be, int CO, int D, int pd) {
    __shared__ float sc[128], sh[128];
    if (threadIdx.x < CO) {
        int c = threadIdx.x;
        float cnt  = fmaxf(stats[2 * CO], 1.f);
        float mean = stats[c] / cnt;
        float var  = stats[CO + c] / cnt - mean * mean;
        float s = g[c] * rsqrtf(var + 1e-5f);
        sc[c] = s;
        sh[c] = be[c] - mean * s;
    }
    __syncthreads();
    const int D3 = D * D * D, P = D + 2 * pd, P3 = P * P * P;
    int idx = blockIdx.x * 256 + threadIdx.x;
    int c = (idx / D3) % CO, b = idx / (D3 * CO), r = idx % D3;
    int rz = r / (D * D), ry = (r / D) % D, rx = r % D;
    int off = (b * CO + c) * P3 + ((rz + pd) * P + (ry + pd)) * P + (rx + pd);
    z[off] = fmaf(z[off], sc[c], sh[c]) * mo[b * D3 + r];
}

// ---------------------------------------------------------------------------
// Head: dense 1x1x1 conv 64->32 on unpadded z5
// ---------------------------------------------------------------------------
__global__ void __launch_bounds__(256) k_head(const float* __restrict__ x,
                                              const float* __restrict__ fwT,
                                              const float* __restrict__ fb,
                                              float* __restrict__ out) {
    __shared__ __align__(16) float sw[64 * 32];
    for (int i = threadIdx.x; i < 2048; i += 256) sw[i] = fwT[i];
    __syncthreads();
    const int D3 = 32768;
    int v = blockIdx.x * 256 + threadIdx.x;
    int b = v / D3, r = v % D3;
    u64 acc2[16];
#pragma unroll
    for (int k = 0; k < 16; k++) acc2[k] = 0ull;
    const float* xp = x + b * 64 * D3 + r;
#pragma unroll 8
    for (int ci = 0; ci < 64; ci++) {
        u64 xv = pack2(*xp); xp += D3;
        const ulonglong2* w2 = reinterpret_cast<const ulonglong2*>(sw + ci * 32);
#pragma unroll
        for (int q = 0; q < 8; q++) {
            ulonglong2 w = w2[q];
            acc2[2 * q]     = ffma2(xv, w.x, acc2[2 * q]);
            acc2[2 * q + 1] = ffma2(xv, w.y, acc2[2 * q + 1]);
        }
    }
#pragma unroll
    for (int k = 0; k < 16; k++) {
        float2 a = unpack2(acc2[k]);
        out[(b * 32 + 2 * k)     * D3 + r] = a.x + fb[2 * k];
        out[(b * 32 + 2 * k + 1) * D3 + r] = a.y + fb[2 * k + 1];
    }
}

// ---------------------------------------------------------------------------
// Host launcher
// ---------------------------------------------------------------------------
extern "C" void kernel_launch(void* const* d_in, const int* in_sizes, int n_in,
                              void* d_out, int out_size) {
    (void)in_sizes; (void)n_in; (void)out_size;
    float* S = nullptr;
    cudaGetSymbolAddress((void**)&S, g_scratch);

    const float* feat = (const float*)d_in[0];
    const float* mask = (const float*)d_in[1];
    const float* w1  = (const float*)d_in[2];  const float* b1  = (const float*)d_in[3];
    const float* g1  = (const float*)d_in[4];  const float* be1 = (const float*)d_in[5];
    const float* w2  = (const float*)d_in[6];  const float* b2  = (const float*)d_in[7];
    const float* g2  = (const float*)d_in[8];  const float* be2 = (const float*)d_in[9];
    const float* w3  = (const float*)d_in[10]; const float* b3  = (const float*)d_in[11];
    const float* g3  = (const float*)d_in[12]; const float* be3 = (const float*)d_in[13];
    const float* tw1 = (const float*)d_in[14]; const float* tb1 = (const float*)d_in[15];
    const float* tg1 = (const float*)d_in[16]; const float* tbe1= (const float*)d_in[17];
    const float* tw2 = (const float*)d_in[18]; const float* tb2 = (const float*)d_in[19];
    const float* tg2 = (const float*)d_in[20]; const float* tbe2= (const float*)d_in[21];
    const float* fw  = (const float*)d_in[22]; const float* fb  = (const float*)d_in[23];
    float* out = (float*)d_out;

    float *x0 = S+OX0, *z1 = S+OZ1, *z2 = S+OZ2, *z3 = S+OZ3, *z4 = S+OZ4, *z5 = S+OZ5;
    float *m0 = S+OM0, *m1 = S+OM1, *m2 = S+OM2, *m3 = S+OM3, *m4 = S+OM4, *m5 = S+OM5;
    float *w1T = S+OW1, *w2T = S+OW2, *w3T = S+OW3, *tw1T = S+OTW1, *tw2T = S+OTW2, *fwT = S+OFW;
    float *st = S+OST;

    k_zero4<<<7140, 256>>>((float4*)S, 7310912 / 4, st, 5 * 260);
    k_trans_all<<<8744, 256>>>(w1, w2, w3, tw1, tw2, fw, S);
    k_pre<<<2048, 256>>>(feat, mask, x0, m0);
    k_maskd_fwd<64, 32><<<256, 256>>>(m0, m1, st + 0 * 260 + 64);
    k_maskd_fwd<32, 16><<<32, 256>>>(m1, m2, st + 1 * 260 + 128);

    // stage 1: 4 -> 32, 64^3 -> 32^3
    k_conv_fwd<4, 32, 64, 32, true, 256><<<dim3(256, 4), 256>>>(x0, w1T, b1, m1, z1, st + 0 * 260);
    k_norm<<<8192, 256>>>(z1, m1, st + 0 * 260, g1, be1, 32, 32, 1);

    // stage 2: 32 -> 64, 32^3 -> 16^3 (2-voxel threads)
    k_conv_fwd2<32, 64, 32, 16><<<dim3(16, 8), 256>>>(z1, w2T, b2, m2, z2, st + 1 * 260);
    k_maskd_fwd<16, 8><<<4, 256>>>(m2, m3, st + 2 * 260 + 256);
    k_norm<<<2048, 256>>>(z2, m2, st + 1 * 260, g2, be2, 64, 16, 1);

    // stage 3: 64 -> 128, 16^3 -> 8^3
    k_conv_fwd<64, 128, 16, 8, false, 128><<<dim3(8, 16), 128>>>(z2, w3T, b3, m3, z3, st + 2 * 260);
    k_norm<<<512, 256>>>(z3, m3, st + 2 * 260, g3, be3, 128, 8, 1);

    // stage 4: tconv 128 -> 128, 8^3 -> 16^3 (padded out, 2-voxel threads)
    k_maskd_t<8, 16><<<32, 256>>>(m3, m4, st + 3 * 260 + 256);
    k_conv_t2<128, 128, 8, true><<<dim3(2, 8, 8), 256>>>(z3, tw1T, tb1, m4, z4, st + 3 * 260);
    k_norm<<<4096, 256>>>(z4, m4, st + 3 * 260, tg1, tbe1, 128, 16, 1);

    // stage 5: tconv 128 -> 64, 16^3 -> 32^3 (unpadded out, 2-voxel threads)
    k_maskd_t<16, 32><<<256, 256>>>(m4, m5, st + 4 * 260 + 128);
    k_conv_t2<128, 64, 16, false><<<dim3(16, 4, 8), 256>>>(z4, tw2T, tb2, m5, z5, st + 4 * 260);
    k_norm<<<16384, 256>>>(z5, m5, st + 4 * 260, tg2, tbe2, 64, 32, 0);

    // head
    k_head<<<256, 256>>>(z5, fwT, fb, out);
}

// round 7
// speedup vs baseline: 1.4834x; 1.3907x over previous
#include <cuda_runtime.h>
#include <math.h>

typedef unsigned long long u64;

__device__ __forceinline__ u64 pack2(float v) {
    u64 r; asm("mov.b64 %0, {%1, %1};" : "=l"(r) : "f"(v)); return r;
}
__device__ __forceinline__ u64 ffma2(u64 a, u64 b, u64 c) {
    u64 d; asm("fma.rn.f32x2 %0, %1, %2, %3;" : "=l"(d) : "l"(a), "l"(b), "l"(c)); return d;
}
__device__ __forceinline__ float2 unpack2(u64 a) {
    float2 f; asm("mov.b64 {%0, %1}, %2;" : "=f"(f.x), "=f"(f.y) : "l"(a)); return f;
}

// ---------------------------------------------------------------------------
// Scratch arena. Activations halo-padded: dim D stored as P=D+2, interior
// voxel (z,y,x) at ((z+1)*P+(y+1))*P+(x+1).
// ---------------------------------------------------------------------------
constexpr int OX0  = 0;          // 2*4*66^3   = 2299968
constexpr int OZ1  = 2299968;    // 2*32*34^3  = 2515456
constexpr int OZ2  = 4815424;    // 2*64*18^3  = 746496
constexpr int OZ3  = 5561920;    // 2*128*10^3 = 256000
constexpr int OZ4  = 5817920;    // 2*128*18^3 = 1492992
constexpr int OZ5  = 7310912;    // 2*64*32^3  = 4194304 (unpadded)
constexpr int OM0  = 11505216;   // 2*64^3
constexpr int OM1  = 12029504;   // 2*32^3
constexpr int OM2  = 12095040;   // 2*16^3
constexpr int OM3  = 12103232;   // 2*8^3
constexpr int OM4  = 12104256;   // 2*16^3
constexpr int OM5  = 12112448;   // 2*32^3
constexpr int OW1  = 12177984;   // 8192
constexpr int OW2  = 12186176;   // 131072
constexpr int OW3  = 12317248;   // 524288
constexpr int OTW1 = 12841536;   // 1048576
constexpr int OTW2 = 13890112;   // 524288
constexpr int OFW  = 14414400;   // 2048
constexpr int OST  = 14416448;   // 5*260
constexpr int OPB  = 14417920;   // partial buffer, 4.2M floats (max of splits)
constexpr int TOT_SCRATCH = 18612224;

__device__ __align__(16) float g_scratch[TOT_SCRATCH];

__global__ void k_zero4(float4* __restrict__ a, int n4, float* __restrict__ st, int nst) {
    int i = blockIdx.x * 256 + threadIdx.x;
    if (i < n4) a[i] = make_float4(0.f, 0.f, 0.f, 0.f);
    if (i < nst) st[i] = 0.f;
}

__global__ void k_pre(const float* __restrict__ feat, const float* __restrict__ mask,
                      float* __restrict__ x0, float* __restrict__ m0) {
    int v = blockIdx.x * 256 + threadIdx.x;
    float m = mask[v] > 0.5f ? 1.f : 0.f;
    m0[v] = m;
    int b = v >> 18, r = v & 262143;
    int z = r >> 12, y = (r >> 6) & 63, x = r & 63;
    int poff = ((z + 1) * 66 + (y + 1)) * 66 + (x + 1);
#pragma unroll
    for (int c = 0; c < 4; c++)
        x0[(b * 4 + c) * 287496 + poff] = feat[(b * 4 + c) * 262144 + r] * m;
}

__global__ void k_trans_all(const float* __restrict__ w1, const float* __restrict__ w2,
                            const float* __restrict__ w3, const float* __restrict__ tw1,
                            const float* __restrict__ tw2, const float* __restrict__ fw,
                            float* __restrict__ S) {
    int idx = blockIdx.x * 256 + threadIdx.x;
    const float* src; float* dst; int CI, CO, i = idx;
    if (i < 8192)            { src = w1;  dst = S + OW1;  CI = 4;   CO = 32;  }
    else if ((i -= 8192)  < 131072)  { src = w2;  dst = S + OW2;  CI = 32;  CO = 64;  }
    else if ((i -= 131072) < 524288) { src = w3;  dst = S + OW3;  CI = 64;  CO = 128; }
    else if ((i -= 524288) < 1048576){ src = tw1; dst = S + OTW1; CI = 128; CO = 128; }
    else if ((i -= 1048576)< 524288) { src = tw2; dst = S + OTW2; CI = 128; CO = 64;  }
    else if ((i -= 524288) < 2048)   { S[OFW + (i % 64) * 32 + i / 64] = fw[i]; return; }
    else return;
    int t = i & 63, ci = (i >> 6) % CI, co = i / (64 * CI);
    dst[(t * CI + ci) * CO + co] = src[i];
}

// ---------------------------------------------------------------------------
// Mask dilation (+ active count into stats[2*CO])
// ---------------------------------------------------------------------------
template <int DI, int DO>
__global__ void k_maskd_fwd(const float* __restrict__ mi, float* __restrict__ mo,
                            float* __restrict__ cnt) {
    const int DO3 = DO * DO * DO, DI2 = DI * DI, DI3 = DI * DI * DI;
    int v = blockIdx.x * 256 + threadIdx.x;
    int b = v / DO3, r = v % DO3;
    int oz = r / (DO * DO), oy = (r / DO) % DO, ox = r % DO;
    float m = 0.f;
    for (int tz = 0; tz < 4; tz++) {
        int iz = 2 * oz - 1 + tz;
        if ((unsigned)iz >= DI) continue;
        for (int ty = 0; ty < 4; ty++) {
            int iy = 2 * oy - 1 + ty;
            if ((unsigned)iy >= DI) continue;
            const float* p = mi + b * DI3 + iz * DI2 + iy * DI;
            for (int tx = 0; tx < 4; tx++) {
                int ix = 2 * ox - 1 + tx;
                if ((unsigned)ix < DI) m += p[ix];
            }
        }
    }
    float act = m > 0.f ? 1.f : 0.f;
    mo[v] = act;
    float s = act;
    for (int o = 16; o; o >>= 1) s += __shfl_xor_sync(0xffffffffu, s, o);
    if ((threadIdx.x & 31) == 0) atomicAdd(cnt, s);
}

template <int DI, int DO>
__global__ void k_maskd_t(const float* __restrict__ mi, float* __restrict__ mo,
                          float* __restrict__ cnt) {
    const int DO3 = DO * DO * DO, DI2 = DI * DI, DI3 = DI * DI * DI;
    int v = blockIdx.x * 256 + threadIdx.x;
    int b = v / DO3, r = v % DO3;
    int oz = r / (DO * DO), oy = (r / DO) % DO, ox = r % DO;
    int izl[2], iyl[2], ixl[2];
    izl[0] = oz >> 1; izl[1] = (oz & 1) ? (oz >> 1) + 1 : (oz >> 1) - 1;
    iyl[0] = oy >> 1; iyl[1] = (oy & 1) ? (oy >> 1) + 1 : (oy >> 1) - 1;
    ixl[0] = ox >> 1; ixl[1] = (ox & 1) ? (ox >> 1) + 1 : (ox >> 1) - 1;
    float m = 0.f;
#pragma unroll
    for (int jz = 0; jz < 2; jz++) {
        int iz = izl[jz];
        if ((unsigned)iz >= DI) continue;
#pragma unroll
        for (int jy = 0; jy < 2; jy++) {
            int iy = iyl[jy];
            if ((unsigned)iy >= DI) continue;
#pragma unroll
            for (int jx = 0; jx < 2; jx++) {
                int ix = ixl[jx];
                if ((unsigned)ix < DI) m += mi[b * DI3 + iz * DI2 + iy * DI + ix];
            }
        }
    }
    float act = m > 0.f ? 1.f : 0.f;
    mo[v] = act;
    float s = act;
    for (int o = 16; o; o >>= 1) s += __shfl_xor_sync(0xffffffffu, s, o);
    if ((threadIdx.x & 31) == 0) atomicAdd(cnt, s);
}

// ---------------------------------------------------------------------------
// Forward conv, 2 adjacent output voxels x 8 co per thread.
// SPLIT=1 : full conv + epilogue (bias/mask/leaky/stats), padded store.
// SPLIT=4 : blockIdx.z = tz, partial sums -> pbuf (zout), no epilogue.
// SPLIT=16: blockIdx.z = tz*4+ty, partial sums -> pbuf.
// ---------------------------------------------------------------------------
template <int CI, int CO, int DI, int DO, int SPLIT>
__global__ void __launch_bounds__(256) k_conv_fwd2(
    const float* __restrict__ x, const float* __restrict__ wT,
    const float* __restrict__ bias, const float* __restrict__ mo,
    float* __restrict__ zout, float* __restrict__ stats) {
    constexpr int PI = DI + 2, PO = DO + 2;
    constexpr int PI2 = PI * PI, PI3 = PI2 * PI, PO3 = PO * PO * PO;
    constexpr int DO3 = DO * DO * DO, HDO3 = DO3 / 2;
    constexpr int NTAP = (SPLIT == 16) ? 4 : 16;
    __shared__ __align__(16) float sw[NTAP * CI * 8];
    const int co0 = blockIdx.y * 8;
    const int v = blockIdx.x * 256 + threadIdx.x;
    const int b = v / HDO3, rp = v % HDO3;
    const int r = 2 * rp;
    const int oz = r / (DO * DO), oy = (r / DO) % DO, ox = r % DO;   // ox even
    u64 aA[4] = {0ull,0ull,0ull,0ull}, aB[4] = {0ull,0ull,0ull,0ull};
    const float* xbase = x + (b * CI) * PI3 + (2 * oz) * PI2 + (2 * oy) * PI + 2 * ox;

    auto stage = [&](int t0, int ntap) {
        for (int i = threadIdx.x; i < ntap * CI * 8; i += 256) {
            int k = i & 7, ci = (i >> 3) % CI, s = i / (8 * CI);
            sw[i] = wT[((t0 + s) * CI + ci) * CO + co0 + k];
        }
    };
    auto body = [&](int tz, int ty, const float* swrow) {
        const float* xr = xbase + tz * PI2 + ty * PI;
#pragma unroll 4
        for (int ci = 0; ci < CI; ci++) {
            const float* xp = xr + ci * PI3;
            float2 x01 = *reinterpret_cast<const float2*>(xp);
            float2 x23 = *reinterpret_cast<const float2*>(xp + 2);
            float2 x45 = *reinterpret_cast<const float2*>(xp + 4);
            u64 p[6];
            p[0] = pack2(x01.x); p[1] = pack2(x01.y); p[2] = pack2(x23.x);
            p[3] = pack2(x23.y); p[4] = pack2(x45.x); p[5] = pack2(x45.y);
#pragma unroll
            for (int tx = 0; tx < 4; tx++) {
                const float* wp = swrow + (tx * CI + ci) * 8;
                ulonglong2 w0 = *reinterpret_cast<const ulonglong2*>(wp);
                ulonglong2 w1 = *reinterpret_cast<const ulonglong2*>(wp + 4);
                aA[0] = ffma2(p[tx], w0.x, aA[0]);
                aA[1] = ffma2(p[tx], w0.y, aA[1]);
                aA[2] = ffma2(p[tx], w1.x, aA[2]);
                aA[3] = ffma2(p[tx], w1.y, aA[3]);
                aB[0] = ffma2(p[tx + 2], w0.x, aB[0]);
                aB[1] = ffma2(p[tx + 2], w0.y, aB[1]);
                aB[2] = ffma2(p[tx + 2], w1.x, aB[2]);
                aB[3] = ffma2(p[tx + 2], w1.y, aB[3]);
            }
        }
    };

    if constexpr (SPLIT == 1) {
        for (int tz = 0; tz < 4; tz++) {
            __syncthreads();
            stage(tz * 16, 16);
            __syncthreads();
            for (int ty = 0; ty < 4; ty++) body(tz, ty, sw + (ty * 4) * CI * 8);
        }
    } else if constexpr (SPLIT == 4) {
        const int tz = blockIdx.z;
        stage(tz * 16, 16);
        __syncthreads();
        for (int ty = 0; ty < 4; ty++) body(tz, ty, sw + (ty * 4) * CI * 8);
    } else {
        const int tz = blockIdx.z >> 2, ty = blockIdx.z & 3;
        stage(tz * 16 + ty * 4, 4);
        __syncthreads();
        body(tz, ty, sw);
    }

    if constexpr (SPLIT == 1) {
        __shared__ float ssum[8], ssq[8];
        const float mA = mo[b * DO3 + r], mB = mo[b * DO3 + r + 1];
        const int poffA = ((oz + 1) * PO + (oy + 1)) * PO + (ox + 1);
        float zsA[8], zsB[8];
#pragma unroll
        for (int p = 0; p < 4; p++) {
            float2 a = unpack2(aA[p]);
            float2 bb = unpack2(aB[p]);
            float bi0 = bias[co0 + 2 * p], bi1 = bias[co0 + 2 * p + 1];
            float yA0 = (a.x + bi0) * mA, yA1 = (a.y + bi1) * mA;
            float yB0 = (bb.x + bi0) * mB, yB1 = (bb.y + bi1) * mB;
            zsA[2*p]   = yA0 >= 0.f ? yA0 : 0.01f * yA0;
            zsA[2*p+1] = yA1 >= 0.f ? yA1 : 0.01f * yA1;
            zsB[2*p]   = yB0 >= 0.f ? yB0 : 0.01f * yB0;
            zsB[2*p+1] = yB1 >= 0.f ? yB1 : 0.01f * yB1;
            float* zp0 = zout + (b * CO + co0 + 2 * p) * PO3 + poffA;
            float* zp1 = zout + (b * CO + co0 + 2 * p + 1) * PO3 + poffA;
            zp0[0] = zsA[2*p];   zp0[1] = zsB[2*p];
            zp1[0] = zsA[2*p+1]; zp1[1] = zsB[2*p+1];
        }
        __syncthreads();
        if (threadIdx.x < 8) { ssum[threadIdx.x] = 0.f; ssq[threadIdx.x] = 0.f; }
        __syncthreads();
#pragma unroll
        for (int k = 0; k < 8; k++) {
            float s = zsA[k] + zsB[k];
            float q = zsA[k] * zsA[k] + zsB[k] * zsB[k];
            for (int o = 16; o; o >>= 1) {
                s += __shfl_xor_sync(0xffffffffu, s, o);
                q += __shfl_xor_sync(0xffffffffu, q, o);
            }
            if ((threadIdx.x & 31) == 0) { atomicAdd(&ssum[k], s); atomicAdd(&ssq[k], q); }
        }
        __syncthreads();
        if (threadIdx.x < 8)
            atomicAdd(&stats[co0 + threadIdx.x], ssum[threadIdx.x]);
        else if (threadIdx.x < 16)
            atomicAdd(&stats[CO + co0 + threadIdx.x - 8], ssq[threadIdx.x - 8]);
    } else {
        float* pb = zout + ((blockIdx.z * 2 + b) * CO) * DO3 + r;
#pragma unroll
        for (int p = 0; p < 4; p++) {
            float2 a = unpack2(aA[p]);
            float2 bb = unpack2(aB[p]);
            *reinterpret_cast<float2*>(pb + (co0 + 2 * p) * DO3)     = make_float2(a.x, bb.x);
            *reinterpret_cast<float2*>(pb + (co0 + 2 * p + 1) * DO3) = make_float2(a.y, bb.y);
        }
    }
}

// ---------------------------------------------------------------------------
// Transpose conv, 2 adjacent input voxels x 16 co per thread, parity classes.
// SPLIT=1: blockIdx.z = cls (8), full epilogue.
// SPLIT=4: blockIdx.z = jp*8+cls (32), partial sums -> pbuf (unpadded DO3).
// ---------------------------------------------------------------------------
template <int CI, int CO, int DI, bool PADOUT, int SPLIT>
__global__ void __launch_bounds__(256) k_conv_t2(
    const float* __restrict__ x, const float* __restrict__ wT,
    const float* __restrict__ bias, const float* __restrict__ mo,
    float* __restrict__ zout, float* __restrict__ stats) {
    constexpr int DO = 2 * DI, PI = DI + 2, PO = DO + 2;
    constexpr int PI2 = PI * PI, PI3 = PI2 * PI;
    constexpr int DI2 = DI * DI, DI3 = DI2 * DI, DO3 = DO * DO * DO;
    constexpr int PO3 = PO * PO * PO, HDI3 = DI3 / 2;
    __shared__ __align__(16) float sw[2 * CI * 16];
    const int cls = (SPLIT == 1) ? blockIdx.z : (blockIdx.z & 7);
    const int jp0 = (SPLIT == 1) ? 0 : (blockIdx.z >> 3);
    const int pz = (cls >> 2) & 1, py = (cls >> 1) & 1, px = cls & 1;
    const int cog = blockIdx.y * 16;
    const int v = blockIdx.x * 256 + threadIdx.x;
    const int b = v / HDI3, rp = v % HDI3;
    const int r = 2 * rp;
    const int zi = r / DI2, yi = (r / DI) % DI, xi = r % DI;   // xi even

    u64 aA[8], aB[8];
#pragma unroll
    for (int k = 0; k < 8; k++) { aA[k] = 0ull; aB[k] = 0ull; }

    const int sxp = (px ? xi : xi - 1) + 1;
    constexpr int NJP = (SPLIT == 1) ? 4 : 1;

    for (int jj = 0; jj < NJP; jj++) {
        const int jp = jp0 + jj;
        const int jz = jp >> 1, jy = jp & 1;
        const int tz = pz ? 2 - 2 * jz : 1 + 2 * jz;
        const int ty = py ? 2 - 2 * jy : 1 + 2 * jy;
        if (jj) __syncthreads();
        for (int i = threadIdx.x; i < 2 * CI * 16; i += 256) {
            int k = i & 15, ci = (i >> 4) % CI, jx = i / (16 * CI);
            int tx = px ? 2 - 2 * jx : 1 + 2 * jx;
            sw[i] = wT[((tz * 16 + ty * 4 + tx) * CI + ci) * CO + cog + k];
        }
        __syncthreads();
        const int iz = pz ? zi + jz : zi - jz;
        const int iy = py ? yi + jy : yi - jy;
        const float* xr = x + (b * CI) * PI3 + (iz + 1) * PI2 + (iy + 1) * PI + sxp;
#pragma unroll 2
        for (int ci = 0; ci < CI; ci++) {
            const float* xp = xr + ci * PI3;
            u64 p0 = pack2(xp[0]), p1 = pack2(xp[1]), p2 = pack2(xp[2]);
            {
                const float* wp = sw + ci * 16;
                ulonglong2 w0 = *reinterpret_cast<const ulonglong2*>(wp);
                ulonglong2 w1 = *reinterpret_cast<const ulonglong2*>(wp + 4);
                ulonglong2 w2 = *reinterpret_cast<const ulonglong2*>(wp + 8);
                ulonglong2 w3 = *reinterpret_cast<const ulonglong2*>(wp + 12);
                u64 xA = px ? p0 : p1;
                u64 xB = px ? p1 : p2;
                aA[0] = ffma2(xA, w0.x, aA[0]); aA[1] = ffma2(xA, w0.y, aA[1]);
                aA[2] = ffma2(xA, w1.x, aA[2]); aA[3] = ffma2(xA, w1.y, aA[3]);
                aA[4] = ffma2(xA, w2.x, aA[4]); aA[5] = ffma2(xA, w2.y, aA[5]);
                aA[6] = ffma2(xA, w3.x, aA[6]); aA[7] = ffma2(xA, w3.y, aA[7]);
                aB[0] = ffma2(xB, w0.x, aB[0]); aB[1] = ffma2(xB, w0.y, aB[1]);
                aB[2] = ffma2(xB, w1.x, aB[2]); aB[3] = ffma2(xB, w1.y, aB[3]);
                aB[4] = ffma2(xB, w2.x, aB[4]); aB[5] = ffma2(xB, w2.y, aB[5]);
                aB[6] = ffma2(xB, w3.x, aB[6]); aB[7] = ffma2(xB, w3.y, aB[7]);
            }
            {
                const float* wp = sw + (CI + ci) * 16;
                ulonglong2 w0 = *reinterpret_cast<const ulonglong2*>(wp);
                ulonglong2 w1 = *reinterpret_cast<const ulonglong2*>(wp + 4);
                ulonglong2 w2 = *reinterpret_cast<const ulonglong2*>(wp + 8);
                ulonglong2 w3 = *reinterpret_cast<const ulonglong2*>(wp + 12);
                u64 xA = px ? p1 : p0;
                u64 xB = px ? p2 : p1;
                aA[0] = ffma2(xA, w0.x, aA[0]); aA[1] = ffma2(xA, w0.y, aA[1]);
                aA[2] = ffma2(xA, w1.x, aA[2]); aA[3] = ffma2(xA, w1.y, aA[3]);
                aA[4] = ffma2(xA, w2.x, aA[4]); aA[5] = ffma2(xA, w2.y, aA[5]);
                aA[6] = ffma2(xA, w3.x, aA[6]); aA[7] = ffma2(xA, w3.y, aA[7]);
                aB[0] = ffma2(xB, w0.x, aB[0]); aB[1] = ffma2(xB, w0.y, aB[1]);
                aB[2] = ffma2(xB, w1.x, aB[2]); aB[3] = ffma2(xB, w1.y, aB[3]);
                aB[4] = ffma2(xB, w2.x, aB[4]); aB[5] = ffma2(xB, w2.y, aB[5]);
                aB[6] = ffma2(xB, w3.x, aB[6]); aB[7] = ffma2(xB, w3.y, aB[7]);
            }
        }
    }

    const int oz = 2 * zi + pz, oy = 2 * yi + py;
    const int oxA = 2 * xi + px;
    const int roA = (oz * DO + oy) * DO + oxA;      // voxel B at roA + 2

    if constexpr (SPLIT == 1) {
        __shared__ float ssum[16], ssq[16];
        const float mA = mo[b * DO3 + roA], mB = mo[b * DO3 + roA + 2];
        const int ooffA = PADOUT ? ((oz + 1) * PO + (oy + 1)) * PO + (oxA + 1) : roA;
        const int ostr  = PADOUT ? PO3 : DO3;
        float zsA[16], zsB[16];
#pragma unroll
        for (int p = 0; p < 8; p++) {
            float2 a = unpack2(aA[p]);
            float2 bb = unpack2(aB[p]);
            float bi0 = bias[cog + 2 * p], bi1 = bias[cog + 2 * p + 1];
            float yA0 = (a.x + bi0) * mA, yA1 = (a.y + bi1) * mA;
            float yB0 = (bb.x + bi0) * mB, yB1 = (bb.y + bi1) * mB;
            zsA[2*p]   = yA0 >= 0.f ? yA0 : 0.01f * yA0;
            zsA[2*p+1] = yA1 >= 0.f ? yA1 : 0.01f * yA1;
            zsB[2*p]   = yB0 >= 0.f ? yB0 : 0.01f * yB0;
            zsB[2*p+1] = yB1 >= 0.f ? yB1 : 0.01f * yB1;
            float* zp0 = zout + (b * CO + cog + 2 * p) * ostr + ooffA;
            float* zp1 = zout + (b * CO + cog + 2 * p + 1) * ostr + ooffA;
            zp0[0] = zsA[2*p];   zp0[2] = zsB[2*p];
            zp1[0] = zsA[2*p+1]; zp1[2] = zsB[2*p+1];
        }
        __syncthreads();
        if (threadIdx.x < 16) { ssum[threadIdx.x] = 0.f; ssq[threadIdx.x] = 0.f; }
        __syncthreads();
#pragma unroll
        for (int k = 0; k < 16; k++) {
            float s = zsA[k] + zsB[k];
            float q = zsA[k] * zsA[k] + zsB[k] * zsB[k];
            for (int o = 16; o; o >>= 1) {
                s += __shfl_xor_sync(0xffffffffu, s, o);
                q += __shfl_xor_sync(0xffffffffu, q, o);
            }
            if ((threadIdx.x & 31) == 0) { atomicAdd(&ssum[k], s); atomicAdd(&ssq[k], q); }
        }
        __syncthreads();
        if (threadIdx.x < 16)
            atomicAdd(&stats[cog + threadIdx.x], ssum[threadIdx.x]);
        else if (threadIdx.x < 32)
            atomicAdd(&stats[CO + cog + threadIdx.x - 16], ssq[threadIdx.x - 16]);
    } else {
        float* pb = zout + ((jp0 * 2 + b) * CO) * DO3;
#pragma unroll
        for (int p = 0; p < 8; p++) {
            float2 a = unpack2(aA[p]);
            float2 bb = unpack2(aB[p]);
            pb[(cog + 2 * p)     * DO3 + roA]     = a.x;
            pb[(cog + 2 * p + 1) * DO3 + roA]     = a.y;
            pb[(cog + 2 * p)     * DO3 + roA + 2] = bb.x;
            pb[(cog + 2 * p + 1) * DO3 + roA + 2] = bb.y;
        }
    }
}

// ---------------------------------------------------------------------------
// Post pass for split convs: sum NS partials, +bias, *mask, leaky, padded
// store, BN stats.
// ---------------------------------------------------------------------------
template <int NS>
__global__ void k_post(const float* __restrict__ pbuf, const float* __restrict__ bias,
                       const float* __restrict__ mo, float* __restrict__ z,
                       float* __restrict__ stats, int CO, int D, int pd) {
    const int D3 = D * D * D;
    int idx = blockIdx.x * 256 + threadIdx.x;
    int r = idx % D3, c = (idx / D3) % CO, b = idx / (D3 * CO);
    float s = 0.f;
#pragma unroll
    for (int j = 0; j < NS; j++) s += pbuf[((j * 2 + b) * CO + c) * D3 + r];
    float m = mo[b * D3 + r];
    float y = (s + bias[c]) * m;
    y = y >= 0.f ? y : 0.01f * y;
    int P = D + 2 * pd, P3 = P * P * P;
    int rz = r / (D * D), ry = (r / D) % D, rx = r % D;
    z[(b * CO + c) * P3 + ((rz + pd) * P + (ry + pd)) * P + (rx + pd)] = y;
    float ss = y, q = y * y;
    for (int o = 16; o; o >>= 1) {
        ss += __shfl_xor_sync(0xffffffffu, ss, o);
        q  += __shfl_xor_sync(0xffffffffu, q, o);
    }
    if ((threadIdx.x & 31) == 0) { atomicAdd(&stats[c], ss); atomicAdd(&stats[CO + c], q); }
}

// ---------------------------------------------------------------------------
// BN apply with inline finalize
// ---------------------------------------------------------------------------
__global__ void k_norm(float* __restrict__ z, const float* __restrict__ mo,
                       const float* __restrict__ stats, const float* __restrict__ g,
                       const float* __restrict__ be, int CO, int D, int pd) {
    __shared__ float sc[128], sh[128];
    if (threadIdx.x < CO) {
        int c = threadIdx.x;
        float cnt  = fmaxf(stats[2 * CO], 1.f);
        float mean = stats[c] / cnt;
        float var  = stats[CO + c] / cnt - mean * mean;
        float s = g[c] * rsqrtf(var + 1e-5f);
        sc[c] = s;
        sh[c] = be[c] - mean * s;
    }
    __syncthreads();
    const int D3 = D * D * D, P = D + 2 * pd, P3 = P * P * P;
    int idx = blockIdx.x * 256 + threadIdx.x;
    int c = (idx / D3) % CO, b = idx / (D3 * CO), r = idx % D3;
    int rz = r / (D * D), ry = (r / D) % D, rx = r % D;
    int off = (b * CO + c) * P3 + ((rz + pd) * P + (ry + pd)) * P + (rx + pd);
    z[off] = fmaf(z[off], sc[c], sh[c]) * mo[b * D3 + r];
}

// ---------------------------------------------------------------------------
// Head: dense 1x1x1 conv 64->32 on unpadded z5
// ---------------------------------------------------------------------------
__global__ void __launch_bounds__(256) k_head(const float* __restrict__ x,
                                              const float* __restrict__ fwT,
                                              const float* __restrict__ fb,
                                              float* __restrict__ out) {
    __shared__ __align__(16) float sw[64 * 32];
    for (int i = threadIdx.x; i < 2048; i += 256) sw[i] = fwT[i];
    __syncthreads();
    const int D3 = 32768;
    int v = blockIdx.x * 256 + threadIdx.x;
    int b = v / D3, r = v % D3;
    u64 acc2[16];
#pragma unroll
    for (int k = 0; k < 16; k++) acc2[k] = 0ull;
    const float* xp = x + b * 64 * D3 + r;
#pragma unroll 8
    for (int ci = 0; ci < 64; ci++) {
        u64 xv = pack2(*xp); xp += D3;
        const ulonglong2* w2 = reinterpret_cast<const ulonglong2*>(sw + ci * 32);
#pragma unroll
        for (int q = 0; q < 8; q++) {
            ulonglong2 w = w2[q];
            acc2[2 * q]     = ffma2(xv, w.x, acc2[2 * q]);
            acc2[2 * q + 1] = ffma2(xv, w.y, acc2[2 * q + 1]);
        }
    }
#pragma unroll
    for (int k = 0; k < 16; k++) {
        float2 a = unpack2(acc2[k]);
        out[(b * 32 + 2 * k)     * D3 + r] = a.x + fb[2 * k];
        out[(b * 32 + 2 * k + 1) * D3 + r] = a.y + fb[2 * k + 1];
    }
}

// ---------------------------------------------------------------------------
// Host launcher
// ---------------------------------------------------------------------------
extern "C" void kernel_launch(void* const* d_in, const int* in_sizes, int n_in,
                              void* d_out, int out_size) {
    (void)in_sizes; (void)n_in; (void)out_size;
    float* S = nullptr;
    cudaGetSymbolAddress((void**)&S, g_scratch);

    const float* feat = (const float*)d_in[0];
    const float* mask = (const float*)d_in[1];
    const float* w1  = (const float*)d_in[2];  const float* b1  = (const float*)d_in[3];
    const float* g1  = (const float*)d_in[4];  const float* be1 = (const float*)d_in[5];
    const float* w2  = (const float*)d_in[6];  const float* b2  = (const float*)d_in[7];
    const float* g2  = (const float*)d_in[8];  const float* be2 = (const float*)d_in[9];
    const float* w3  = (const float*)d_in[10]; const float* b3  = (const float*)d_in[11];
    const float* g3  = (const float*)d_in[12]; const float* be3 = (const float*)d_in[13];
    const float* tw1 = (const float*)d_in[14]; const float* tb1 = (const float*)d_in[15];
    const float* tg1 = (const float*)d_in[16]; const float* tbe1= (const float*)d_in[17];
    const float* tw2 = (const float*)d_in[18]; const float* tb2 = (const float*)d_in[19];
    const float* tg2 = (const float*)d_in[20]; const float* tbe2= (const float*)d_in[21];
    const float* fw  = (const float*)d_in[22]; const float* fb  = (const float*)d_in[23];
    float* out = (float*)d_out;

    float *x0 = S+OX0, *z1 = S+OZ1, *z2 = S+OZ2, *z3 = S+OZ3, *z4 = S+OZ4, *z5 = S+OZ5;
    float *m0 = S+OM0, *m1 = S+OM1, *m2 = S+OM2, *m3 = S+OM3, *m4 = S+OM4, *m5 = S+OM5;
    float *w1T = S+OW1, *w2T = S+OW2, *w3T = S+OW3, *tw1T = S+OTW1, *tw2T = S+OTW2, *fwT = S+OFW;
    float *st = S+OST, *pb = S+OPB;

    k_zero4<<<7140, 256>>>((float4*)S, 7310912 / 4, st, 5 * 260);
    k_trans_all<<<8744, 256>>>(w1, w2, w3, tw1, tw2, fw, S);
    k_pre<<<2048, 256>>>(feat, mask, x0, m0);
    k_maskd_fwd<64, 32><<<256, 256>>>(m0, m1, st + 0 * 260 + 64);
    k_maskd_fwd<32, 16><<<32, 256>>>(m1, m2, st + 1 * 260 + 128);

    // stage 1: 4 -> 32, 64^3 -> 32^3, 2-voxel threads, 512 CTAs
    k_conv_fwd2<4, 32, 64, 32, 1><<<dim3(128, 4), 256>>>(x0, w1T, b1, m1, z1, st + 0 * 260);
    k_norm<<<8192, 256>>>(z1, m1, st + 0 * 260, g1, be1, 32, 32, 1);

    // stage 2: 32 -> 64, 32^3 -> 16^3, tz-split x4 -> 512 CTAs
    k_conv_fwd2<32, 64, 32, 16, 4><<<dim3(16, 8, 4), 256>>>(z1, w2T, b2, m2, pb, st + 1 * 260);
    k_post<4><<<2048, 256>>>(pb, b2, m2, z2, st + 1 * 260, 64, 16, 1);
    k_maskd_fwd<16, 8><<<4, 256>>>(m2, m3, st + 2 * 260 + 256);
    k_norm<<<2048, 256>>>(z2, m2, st + 1 * 260, g2, be2, 64, 16, 1);

    // stage 3: 64 -> 128, 16^3 -> 8^3, (tz,ty)-split x16 -> 512 CTAs
    k_conv_fwd2<64, 128, 16, 8, 16><<<dim3(2, 16, 16), 256>>>(z2, w3T, b3, m3, pb, st + 2 * 260);
    k_post<16><<<512, 256>>>(pb, b3, m3, z3, st + 2 * 260, 128, 8, 1);
    k_norm<<<512, 256>>>(z3, m3, st + 2 * 260, g3, be3, 128, 8, 1);

    // stage 4: tconv 128 -> 128, 8^3 -> 16^3, jp-split x4 -> 512 CTAs
    k_maskd_t<8, 16><<<32, 256>>>(m3, m4, st + 3 * 260 + 256);
    k_conv_t2<128, 128, 8, true, 4><<<dim3(2, 8, 32), 256>>>(z3, tw1T, tb1, m4, pb, st + 3 * 260);
    k_post<4><<<4096, 256>>>(pb, tb1, m4, z4, st + 3 * 260, 128, 16, 1);
    k_norm<<<4096, 256>>>(z4, m4, st + 3 * 260, tg1, tbe1, 128, 16, 1);

    // stage 5: tconv 128 -> 64, 16^3 -> 32^3, unsplit (28 warps/SM already)
    k_maskd_t<16, 32><<<256, 256>>>(m4, m5, st + 4 * 260 + 128);
    k_conv_t2<128, 64, 16, false, 1><<<dim3(16, 4, 8), 256>>>(z4, tw2T, tb2, m5, z5, st + 4 * 260);
    k_norm<<<16384, 256>>>(z5, m5, st + 4 * 260, tg2, tbe2, 64, 32, 0);

    // head
    k_head<<<256, 256>>>(z5, fwT, fb, out);
}